// round 2
// baseline (speedup 1.0000x reference)
#include <cuda_runtime.h>
#include <math.h>

#define B 64
#define S 256
#define INSZ 128
#define H 512
#define G4 2048          // 4*H
#define NTOK (B*S)       // 16384

// ---------------- scratch (device globals; no allocation allowed) ----------------
__device__ float g_xg[(size_t)NTOK * G4];        // 128 MB: gate pre-activations per layer
__device__ float g_hseq[(size_t)NTOK * H];       // 32 MB: layer-0 hidden sequence (rows n = t*64+b)
__device__ float g_h[2][H * B];                  // double-buffered hidden state, layout [k][b]
__device__ float g_c[H * B];                     // cell state, layout [k][b]
__device__ float g_wdup[2][(size_t)G4 * H * 2];  // 16 MB: W_hh duplicated {w,w}, blocked per CTA

typedef unsigned long long ull;

__device__ __forceinline__ ull pack2(float lo, float hi) {
    ull r; asm("mov.b64 %0, {%1, %2};" : "=l"(r) : "f"(lo), "f"(hi)); return r;
}
__device__ __forceinline__ void unpack2(ull v, float& lo, float& hi) {
    asm("mov.b64 {%0, %1}, %2;" : "=f"(lo), "=f"(hi) : "l"(v));
}
__device__ __forceinline__ void fma2(ull& d, ull a, ull b) {
    asm("fma.rn.f32x2 %0, %1, %2, %0;" : "+l"(d) : "l"(a), "l"(b));
}

// ---------------- prep: duplicate W_hh into CTA-blocked {w,w} layout ----------------
// dst[l][ ((j*4+g)*512 + k)*2 + {0,1} ] = W_hh_l[(g*512+j)*512 + k]
__global__ void prep_wdup_kernel(const float* __restrict__ W0, const float* __restrict__ W1) {
    int idx = blockIdx.x * blockDim.x + threadIdx.x;   // 2 * 2^20 total
    int l = idx >> 20;
    int r = idx & ((1 << 20) - 1);
    int j = r >> 11;
    int g = (r >> 9) & 3;
    int k = r & 511;
    const float* W = l ? W1 : W0;
    float v = W[(g * 512 + j) * 512 + k];
    float* dst = &g_wdup[l][(((size_t)(j * 4 + g)) * 512 + k) * 2];
    dst[0] = v; dst[1] = v;
}

// ---------------- zero h[0] and c ----------------
__global__ void zero_state_kernel() {
    int i = blockIdx.x * blockDim.x + threadIdx.x;
    if (i < H * B) { g_h[0][i] = 0.0f; g_c[i] = 0.0f; }
}

// ---------------- big GEMM: C[m][n] = A[m][:] . W[n][:] + b1[n] + b2[n] ----------------
// A: M x K row-major (layer0: x, layer1: g_hseq). W: 2048 x K row-major. C = g_xg.
#define BM 128
#define BN 128
#define BKT 16
#define LDT 132

__global__ __launch_bounds__(256) void gemm_bias_kernel(
    const float* __restrict__ x_in, const float* __restrict__ W,
    const float* __restrict__ b1, const float* __restrict__ b2,
    int K, int layer)
{
    const float* A = (layer == 0) ? x_in : g_hseq;
    __shared__ __align__(16) float As[BKT][LDT];
    __shared__ __align__(16) float Bs[BKT][LDT];
    int tid = threadIdx.x;
    int m0 = blockIdx.y * BM, n0 = blockIdx.x * BN;
    int tx = tid & 15, ty = tid >> 4;

    ull acc[8][4];
    #pragma unroll
    for (int i = 0; i < 8; i++)
        #pragma unroll
        for (int j = 0; j < 4; j++) acc[i][j] = 0ull;

    for (int k0 = 0; k0 < K; k0 += BKT) {
        #pragma unroll
        for (int r = 0; r < 2; r++) {
            int f = tid + r * 256;
            int m = f >> 2, kq = (f & 3) * 4;
            float4 va = __ldg((const float4*)&A[(size_t)(m0 + m) * K + k0 + kq]);
            As[kq + 0][m] = va.x; As[kq + 1][m] = va.y;
            As[kq + 2][m] = va.z; As[kq + 3][m] = va.w;
            float4 vb = __ldg((const float4*)&W[(size_t)(n0 + m) * K + k0 + kq]);
            Bs[kq + 0][m] = vb.x; Bs[kq + 1][m] = vb.y;
            Bs[kq + 2][m] = vb.z; Bs[kq + 3][m] = vb.w;
        }
        __syncthreads();
        #pragma unroll
        for (int k = 0; k < BKT; k++) {
            float4 a0 = *(const float4*)&As[k][ty * 8];
            float4 a1 = *(const float4*)&As[k][ty * 8 + 4];
            ulonglong2 bb0 = *(const ulonglong2*)&Bs[k][tx * 8];
            ulonglong2 bb1 = *(const ulonglong2*)&Bs[k][tx * 8 + 4];
            ull bb[4] = {bb0.x, bb0.y, bb1.x, bb1.y};
            float av[8] = {a0.x, a0.y, a0.z, a0.w, a1.x, a1.y, a1.z, a1.w};
            #pragma unroll
            for (int i = 0; i < 8; i++) {
                ull ad = pack2(av[i], av[i]);
                #pragma unroll
                for (int j = 0; j < 4; j++) fma2(acc[i][j], ad, bb[j]);
            }
        }
        __syncthreads();
    }

    float bs[8];
    #pragma unroll
    for (int j = 0; j < 8; j++) {
        int n = n0 + tx * 8 + j;
        bs[j] = __ldg(&b1[n]) + __ldg(&b2[n]);
    }
    #pragma unroll
    for (int i = 0; i < 8; i++) {
        int m = m0 + ty * 8 + i;
        float o[8];
        #pragma unroll
        for (int j = 0; j < 4; j++) {
            float lo, hi; unpack2(acc[i][j], lo, hi);
            o[j * 2] = lo + bs[j * 2]; o[j * 2 + 1] = hi + bs[j * 2 + 1];
        }
        float4* dst = (float4*)&g_xg[(size_t)m * G4 + n0 + tx * 8];
        dst[0] = make_float4(o[0], o[1], o[2], o[3]);
        dst[1] = make_float4(o[4], o[5], o[6], o[7]);
    }
}

// ---------------- one LSTM timestep ----------------
// grid 128 CTAs (4 hidden units each), 128 threads = 32 batch-pairs x 4 units.
// Reads h_in = g_h[t&1] (full), writes g_h[(t+1)&1] / g_c for its units only.
__global__ __launch_bounds__(128) void lstm_step_kernel(int t, int layer)
{
    extern __shared__ __align__(16) float Wd[];  // 16384 floats = 64KB: [u][g][k][2]
    int tid = threadIdx.x;

    // stage this CTA's duplicated W_hh slice (contiguous, conflict-free copy)
    const float4* src = (const float4*)&g_wdup[layer][(size_t)blockIdx.x * 16384];
    float4* dst = (float4*)Wd;
    #pragma unroll
    for (int i = 0; i < 32; i++) dst[tid + i * 128] = __ldg(&src[tid + i * 128]);
    __syncthreads();

    int bq = tid & 31;        // batch pair index (2 batches per thread)
    int u  = tid >> 5;        // unit within CTA (warp-uniform -> W LDS is broadcast)
    int b0 = bq * 2;
    const float* __restrict__ h_in = g_h[t & 1];
    const float* Wu = Wd + u * 4096;

    ull acc[4] = {0ull, 0ull, 0ull, 0ull};   // i,f,g,o for batch pair

    #pragma unroll 4
    for (int k = 0; k < H; k += 2) {
        ull h0 = __ldg((const ull*)&h_in[k * 64 + b0]);        // {h[k][b0], h[k][b0+1]}
        ull h1 = __ldg((const ull*)&h_in[(k + 1) * 64 + b0]);
        #pragma unroll
        for (int g = 0; g < 4; g++) {
            ulonglong2 w = *(const ulonglong2*)&Wu[(g * 512 + k) * 2]; // {w_k dup, w_k+1 dup}
            fma2(acc[g], h0, w.x);
            fma2(acc[g], h1, w.y);
        }
    }

    int j = blockIdx.x * 4 + u;
    float ga[4][2];
    #pragma unroll
    for (int g = 0; g < 4; g++) unpack2(acc[g], ga[g][0], ga[g][1]);

    const float* xgb; size_t bstr;
    if (layer == 0) { xgb = g_xg + (size_t)t * G4;      bstr = (size_t)S * G4; } // rows b*S+t
    else            { xgb = g_xg + (size_t)t * B * G4;  bstr = (size_t)G4;     } // rows t*B+b

    float* h_out = g_h[(t + 1) & 1];
    #pragma unroll
    for (int bi = 0; bi < 2; bi++) {
        int b = b0 + bi;
        const float* xr = xgb + (size_t)b * bstr + j;
        float gi = ga[0][bi] + xr[0];
        float gf = ga[1][bi] + xr[512];
        float gg = ga[2][bi] + xr[1024];
        float go = ga[3][bi] + xr[1536];
        float i_ = 1.0f / (1.0f + expf(-gi));
        float f_ = 1.0f / (1.0f + expf(-gf));
        float gt = tanhf(gg);
        float o_ = 1.0f / (1.0f + expf(-go));
        int si = j * 64 + b;
        float c_ = f_ * g_c[si] + i_ * gt;
        g_c[si] = c_;
        float hh = o_ * tanhf(c_);
        h_out[si] = hh;
        if (layer == 0) g_hseq[((size_t)t * 64 + b) * 512 + j] = hh;  // row n = t*64+b
    }
}

// ---------------- final FC: out[b][o] = h_last[:,b] . W_fc[o][:] + b_fc[o] ----------------
__global__ void fc_kernel(const float* __restrict__ Wfc, const float* __restrict__ bfc,
                          float* __restrict__ out)
{
    __shared__ float hcol[H];
    int b = blockIdx.x;
    int o = threadIdx.x;   // 64 threads
    for (int k = o; k < H; k += 64) hcol[k] = g_h[0][k * 64 + b];
    __syncthreads();
    float acc = __ldg(&bfc[o]);
    #pragma unroll 8
    for (int k = 0; k < H; k++) acc += hcol[k] * __ldg(&Wfc[o * 512 + k]);
    out[b * 64 + o] = acc;
}

// ---------------- launch ----------------
extern "C" void kernel_launch(void* const* d_in, const int* in_sizes, int n_in,
                              void* d_out, int out_size)
{
    const float* x      = (const float*)d_in[0];
    const float* W_ih_0 = (const float*)d_in[1];
    const float* W_hh_0 = (const float*)d_in[2];
    const float* b_ih_0 = (const float*)d_in[3];
    const float* b_hh_0 = (const float*)d_in[4];
    const float* W_ih_1 = (const float*)d_in[5];
    const float* W_hh_1 = (const float*)d_in[6];
    const float* b_ih_1 = (const float*)d_in[7];
    const float* b_hh_1 = (const float*)d_in[8];
    const float* W_fc   = (const float*)d_in[9];
    const float* b_fc   = (const float*)d_in[10];
    float* out = (float*)d_out;

    cudaFuncSetAttribute(lstm_step_kernel, cudaFuncAttributeMaxDynamicSharedMemorySize, 65536);

    // W_hh -> duplicated blocked layout (once per graph replay; cheap)
    prep_wdup_kernel<<<8192, 256>>>(W_hh_0, W_hh_1);

    // ---- layer 0 ----
    zero_state_kernel<<<128, 256>>>();
    gemm_bias_kernel<<<dim3(16, 128), 256>>>(x, W_ih_0, b_ih_0, b_hh_0, INSZ, 0);
    for (int t = 0; t < S; t++)
        lstm_step_kernel<<<128, 128, 65536>>>(t, 0);

    // ---- layer 1 ----
    zero_state_kernel<<<128, 256>>>();
    gemm_bias_kernel<<<dim3(16, 128), 256>>>(x, W_ih_1, b_ih_1, b_hh_1, H, 1);
    for (int t = 0; t < S; t++)
        lstm_step_kernel<<<128, 128, 65536>>>(t, 1);

    // ---- head ----
    fc_kernel<<<64, 64>>>(W_fc, b_fc, out);
}

// round 3
// speedup vs baseline: 1.7773x; 1.7773x over previous
#include <cuda_runtime.h>
#include <math.h>

#define B 64
#define S 256
#define INSZ 128
#define H 512
#define G4 2048          // 4*H
#define NTOK (B*S)       // 16384
#define NCTA 128

// ---------------- scratch (device globals; no allocation allowed) ----------------
__device__ float g_xg[(size_t)NTOK * G4];        // 128 MB: gate pre-activations per layer
__device__ float g_hseq[(size_t)NTOK * H];       // 32 MB: layer-0 hidden sequence (rows n = t*64+b)
__device__ float g_h[2][H * B];                  // double-buffered hidden state, layout [k][b]
__device__ float g_wdup[2][(size_t)G4 * H * 2];  // 16 MB: W_hh duplicated {w,w}, blocked per CTA

// grid barrier state (persists across replays; relative-gen logic is replay-safe)
__device__ unsigned g_bar_cnt = 0;
__device__ volatile unsigned g_bar_gen = 0;

typedef unsigned long long ull;

__device__ __forceinline__ ull pack2(float lo, float hi) {
    ull r; asm("mov.b64 %0, {%1, %2};" : "=l"(r) : "f"(lo), "f"(hi)); return r;
}
__device__ __forceinline__ void unpack2(ull v, float& lo, float& hi) {
    asm("mov.b64 {%0, %1}, %2;" : "=f"(lo), "=f"(hi) : "l"(v));
}
__device__ __forceinline__ void fma2(ull& d, ull a, ull b) {
    asm("fma.rn.f32x2 %0, %1, %2, %0;" : "+l"(d) : "l"(a), "l"(b));
}
__device__ __forceinline__ ull add2(ull a, ull b) {
    ull r; asm("add.rn.f32x2 %0, %1, %2;" : "=l"(r) : "l"(a), "l"(b)); return r;
}
__device__ __forceinline__ ull ldcg64(const float* p) {
    ull v; asm volatile("ld.global.cg.b64 %0, [%1];" : "=l"(v) : "l"(p)); return v;
}
__device__ __forceinline__ float ldcs32(const float* p) {
    float v; asm volatile("ld.global.cs.b32 %0, [%1];" : "=f"(v) : "l"(p)); return v;
}
__device__ __forceinline__ float sigm(float x) { return 1.0f / (1.0f + __expf(-x)); }

// ---------------- prep: duplicate W_hh into CTA-blocked {w,w} layout ----------------
__global__ void prep_wdup_kernel(const float* __restrict__ W0, const float* __restrict__ W1) {
    int idx = blockIdx.x * blockDim.x + threadIdx.x;   // 2 * 2^20 total
    int l = idx >> 20;
    int r = idx & ((1 << 20) - 1);
    int j = r >> 11;
    int g = (r >> 9) & 3;
    int k = r & 511;
    const float* W = l ? W1 : W0;
    float v = W[(g * 512 + j) * 512 + k];
    float* dst = &g_wdup[l][(((size_t)(j * 4 + g)) * 512 + k) * 2];
    dst[0] = v; dst[1] = v;
}

// ---------------- zero h[0] ----------------
__global__ void zero_state_kernel() {
    int i = blockIdx.x * blockDim.x + threadIdx.x;
    if (i < H * B) g_h[0][i] = 0.0f;
}

// ---------------- big GEMM: C[m][n] = A[m][:] . W[n][:] + b1[n] + b2[n] ----------------
#define BM 128
#define BN 128
#define BKT 16
#define LDT 132

__global__ __launch_bounds__(256) void gemm_bias_kernel(
    const float* __restrict__ x_in, const float* __restrict__ W,
    const float* __restrict__ b1, const float* __restrict__ b2,
    int K, int layer)
{
    const float* A = (layer == 0) ? x_in : g_hseq;
    __shared__ __align__(16) float As[BKT][LDT];
    __shared__ __align__(16) float Bs[BKT][LDT];
    int tid = threadIdx.x;
    int m0 = blockIdx.y * BM, n0 = blockIdx.x * BN;
    int tx = tid & 15, ty = tid >> 4;

    ull acc[8][4];
    #pragma unroll
    for (int i = 0; i < 8; i++)
        #pragma unroll
        for (int j = 0; j < 4; j++) acc[i][j] = 0ull;

    for (int k0 = 0; k0 < K; k0 += BKT) {
        #pragma unroll
        for (int r = 0; r < 2; r++) {
            int f = tid + r * 256;
            int m = f >> 2, kq = (f & 3) * 4;
            float4 va = __ldg((const float4*)&A[(size_t)(m0 + m) * K + k0 + kq]);
            As[kq + 0][m] = va.x; As[kq + 1][m] = va.y;
            As[kq + 2][m] = va.z; As[kq + 3][m] = va.w;
            float4 vb = __ldg((const float4*)&W[(size_t)(n0 + m) * K + k0 + kq]);
            Bs[kq + 0][m] = vb.x; Bs[kq + 1][m] = vb.y;
            Bs[kq + 2][m] = vb.z; Bs[kq + 3][m] = vb.w;
        }
        __syncthreads();
        #pragma unroll
        for (int k = 0; k < BKT; k++) {
            float4 a0 = *(const float4*)&As[k][ty * 8];
            float4 a1 = *(const float4*)&As[k][ty * 8 + 4];
            ulonglong2 bb0 = *(const ulonglong2*)&Bs[k][tx * 8];
            ulonglong2 bb1 = *(const ulonglong2*)&Bs[k][tx * 8 + 4];
            ull bb[4] = {bb0.x, bb0.y, bb1.x, bb1.y};
            float av[8] = {a0.x, a0.y, a0.z, a0.w, a1.x, a1.y, a1.z, a1.w};
            #pragma unroll
            for (int i = 0; i < 8; i++) {
                ull ad = pack2(av[i], av[i]);
                #pragma unroll
                for (int j = 0; j < 4; j++) fma2(acc[i][j], ad, bb[j]);
            }
        }
        __syncthreads();
    }

    float bs[8];
    #pragma unroll
    for (int j = 0; j < 8; j++) {
        int n = n0 + tx * 8 + j;
        bs[j] = __ldg(&b1[n]) + __ldg(&b2[n]);
    }
    #pragma unroll
    for (int i = 0; i < 8; i++) {
        int m = m0 + ty * 8 + i;
        float o[8];
        #pragma unroll
        for (int j = 0; j < 4; j++) {
            float lo, hi; unpack2(acc[i][j], lo, hi);
            o[j * 2] = lo + bs[j * 2]; o[j * 2 + 1] = hi + bs[j * 2 + 1];
        }
        float4* dst = (float4*)&g_xg[(size_t)m * G4 + n0 + tx * 8];
        dst[0] = make_float4(o[0], o[1], o[2], o[3]);
        dst[1] = make_float4(o[4], o[5], o[6], o[7]);
    }
}

// ---------------- persistent LSTM recurrence (all 256 steps in one launch) ----------------
// 128 CTAs x 256 threads. CTA owns 4 hidden units (64KB W slice in SMEM, loaded once).
// warp w: u = w&3 (unit), kh = w>>2 (k-half). Thread: batch pair b0 = 2*lane.
// c lives in registers of the kh==0 warps for the whole sequence.
__global__ __launch_bounds__(256) void lstm_persist_kernel(int layer)
{
    extern __shared__ __align__(16) float Wd[];   // 64KB: [u][g][k][2]
    __shared__ __align__(16) ull red[4][32][4];   // 4KB k-half reduction

    int tid = threadIdx.x;
    int lane = tid & 31;
    int w = tid >> 5;
    int u = w & 3;
    int kh = w >> 2;
    int b0 = lane * 2;
    int j = blockIdx.x * 4 + u;

    // stage W slice once
    {
        const float4* src = (const float4*)&g_wdup[layer][(size_t)blockIdx.x * 16384];
        float4* dst = (float4*)Wd;
        #pragma unroll
        for (int i = 0; i < 16; i++) dst[tid + i * 256] = __ldg(&src[tid + i * 256]);
    }
    __syncthreads();

    const float* Wuk = Wd + u * 4096 + kh * 512;  // (g*512 + kh*256 + kk)*2 = g*1024 + kh*512 + kk*2
    float c0 = 0.0f, c1 = 0.0f;

    for (int t = 0; t < S; t++) {
        // prefetch x gates early (latency hides under the k-loop)
        float xg0[4], xg1[4];
        if (kh == 0) {
            size_t base0, base1;
            if (layer == 0) {
                base0 = ((size_t)(b0 * S + t)) * G4 + j;
                base1 = ((size_t)((b0 + 1) * S + t)) * G4 + j;
            } else {
                base0 = ((size_t)(t * B + b0)) * G4 + j;
                base1 = base0 + G4;
            }
            #pragma unroll
            for (int g = 0; g < 4; g++) {
                xg0[g] = ldcs32(&g_xg[base0 + g * 512]);
                xg1[g] = ldcs32(&g_xg[base1 + g * 512]);
            }
        }

        ull acc[4] = {0ull, 0ull, 0ull, 0ull};
        if (t > 0) {
            const float* hp = g_h[t & 1] + (size_t)kh * 256 * 64 + b0;
            #pragma unroll 4
            for (int kk = 0; kk < 256; kk += 2) {
                ull h0 = ldcg64(hp + kk * 64);
                ull h1 = ldcg64(hp + (kk + 1) * 64);
                #pragma unroll
                for (int g = 0; g < 4; g++) {
                    ulonglong2 wv = *(const ulonglong2*)&Wuk[g * 1024 + kk * 2];
                    fma2(acc[g], h0, wv.x);
                    fma2(acc[g], h1, wv.y);
                }
            }
        }

        if (kh == 1) {
            #pragma unroll
            for (int g = 0; g < 4; g++) red[u][lane][g] = acc[g];
        }
        __syncthreads();

        if (kh == 0) {
            float ga[4][2];
            #pragma unroll
            for (int g = 0; g < 4; g++) {
                ull s = add2(acc[g], red[u][lane][g]);
                unpack2(s, ga[g][0], ga[g][1]);
            }
            // batch b0
            float i0 = sigm(ga[0][0] + xg0[0]);
            float f0 = sigm(ga[1][0] + xg0[1]);
            float g0 = tanhf(ga[2][0] + xg0[2]);
            float o0 = sigm(ga[3][0] + xg0[3]);
            c0 = f0 * c0 + i0 * g0;
            float hh0 = o0 * tanhf(c0);
            // batch b0+1
            float i1 = sigm(ga[0][1] + xg1[0]);
            float f1 = sigm(ga[1][1] + xg1[1]);
            float g1 = tanhf(ga[2][1] + xg1[2]);
            float o1 = sigm(ga[3][1] + xg1[3]);
            c1 = f1 * c1 + i1 * g1;
            float hh1 = o1 * tanhf(c1);

            *(float2*)&g_h[(t + 1) & 1][j * 64 + b0] = make_float2(hh0, hh1);
            if (layer == 0) {
                g_hseq[((size_t)t * 64 + b0) * 512 + j] = hh0;
                g_hseq[((size_t)t * 64 + b0 + 1) * 512 + j] = hh1;
            }
        }

        // grid barrier (skip after last step; kernel boundary handles final visibility)
        if (t != S - 1) {
            __syncthreads();
            if (tid == 0) {
                unsigned gen = g_bar_gen;
                __threadfence();
                if (atomicAdd(&g_bar_cnt, 1u) == NCTA - 1) {
                    g_bar_cnt = 0;
                    __threadfence();
                    g_bar_gen = gen + 1;
                } else {
                    while (g_bar_gen == gen) { }
                }
                __threadfence();
            }
            __syncthreads();
        }
    }
}

// ---------------- final FC: out[b][o] = h_last[:,b] . W_fc[o][:] + b_fc[o] ----------------
__global__ void fc_kernel(const float* __restrict__ Wfc, const float* __restrict__ bfc,
                          float* __restrict__ out)
{
    __shared__ float hcol[H];
    int b = blockIdx.x;
    int o = threadIdx.x;   // 64 threads
    for (int k = o; k < H; k += 64) hcol[k] = g_h[0][k * 64 + b];
    __syncthreads();
    float acc = __ldg(&bfc[o]);
    #pragma unroll 8
    for (int k = 0; k < H; k++) acc += hcol[k] * __ldg(&Wfc[o * 512 + k]);
    out[b * 64 + o] = acc;
}

// ---------------- launch ----------------
extern "C" void kernel_launch(void* const* d_in, const int* in_sizes, int n_in,
                              void* d_out, int out_size)
{
    const float* x      = (const float*)d_in[0];
    const float* W_ih_0 = (const float*)d_in[1];
    const float* W_hh_0 = (const float*)d_in[2];
    const float* b_ih_0 = (const float*)d_in[3];
    const float* b_hh_0 = (const float*)d_in[4];
    const float* W_ih_1 = (const float*)d_in[5];
    const float* W_hh_1 = (const float*)d_in[6];
    const float* b_ih_1 = (const float*)d_in[7];
    const float* b_hh_1 = (const float*)d_in[8];
    const float* W_fc   = (const float*)d_in[9];
    const float* b_fc   = (const float*)d_in[10];
    float* out = (float*)d_out;

    cudaFuncSetAttribute(lstm_persist_kernel, cudaFuncAttributeMaxDynamicSharedMemorySize, 65536);

    prep_wdup_kernel<<<8192, 256>>>(W_hh_0, W_hh_1);

    // ---- layer 0 ----
    zero_state_kernel<<<128, 256>>>();
    gemm_bias_kernel<<<dim3(16, 128), 256>>>(x, W_ih_0, b_ih_0, b_hh_0, INSZ, 0);
    lstm_persist_kernel<<<NCTA, 256, 65536>>>(0);

    // ---- layer 1 ----
    zero_state_kernel<<<128, 256>>>();
    gemm_bias_kernel<<<dim3(16, 128), 256>>>(x, W_ih_1, b_ih_1, b_hh_1, H, 1);
    lstm_persist_kernel<<<NCTA, 256, 65536>>>(1);

    // ---- head ----
    fc_kernel<<<64, 64>>>(W_fc, b_fc, out);
}

// round 4
// speedup vs baseline: 3.4150x; 1.9215x over previous
#include <cuda_runtime.h>
#include <math.h>

#define B 64
#define S 256
#define INSZ 128
#define H 512
#define G4 2048          // 4*H
#define NTOK (B*S)       // 16384
#define NCTA 128

// ---------------- scratch (device globals; no allocation allowed) ----------------
__device__ float g_xg[(size_t)NTOK * G4];        // 128 MB: gate pre-activations per layer
__device__ float g_hseq[(size_t)NTOK * H];       // 32 MB: layer-0 hidden sequence (rows n = t*64+b)
__device__ float g_h[2][H * B];                  // double-buffered hidden state, layout [k][b]
__device__ float g_wdup[2][(size_t)G4 * H * 2];  // 16 MB: W_hh duplicated {w,w}, blocked per CTA

// grid barrier state (persists across replays; relative-gen logic is replay-safe)
__device__ unsigned g_bar_cnt = 0;
__device__ volatile unsigned g_bar_gen = 0;

typedef unsigned long long ull;

__device__ __forceinline__ ull pack2(float lo, float hi) {
    ull r; asm("mov.b64 %0, {%1, %2};" : "=l"(r) : "f"(lo), "f"(hi)); return r;
}
__device__ __forceinline__ void unpack2(ull v, float& lo, float& hi) {
    asm("mov.b64 {%0, %1}, %2;" : "=f"(lo), "=f"(hi) : "l"(v));
}
__device__ __forceinline__ void fma2(ull& d, ull a, ull b) {
    asm("fma.rn.f32x2 %0, %1, %2, %0;" : "+l"(d) : "l"(a), "l"(b));
}
__device__ __forceinline__ ull add2(ull a, ull b) {
    ull r; asm("add.rn.f32x2 %0, %1, %2;" : "=l"(r) : "l"(a), "l"(b)); return r;
}
__device__ __forceinline__ float ldcs32(const float* p) {
    float v; asm volatile("ld.global.cs.b32 %0, [%1];" : "=f"(v) : "l"(p)); return v;
}
__device__ __forceinline__ float sigm(float x) { return 1.0f / (1.0f + __expf(-x)); }

// ---------------- prep: duplicate W_hh into CTA-blocked {w,w} layout ----------------
__global__ void prep_wdup_kernel(const float* __restrict__ W0, const float* __restrict__ W1) {
    int idx = blockIdx.x * blockDim.x + threadIdx.x;   // 2 * 2^20 total
    int l = idx >> 20;
    int r = idx & ((1 << 20) - 1);
    int j = r >> 11;
    int g = (r >> 9) & 3;
    int k = r & 511;
    const float* W = l ? W1 : W0;
    float v = W[(g * 512 + j) * 512 + k];
    float* dst = &g_wdup[l][(((size_t)(j * 4 + g)) * 512 + k) * 2];
    dst[0] = v; dst[1] = v;
}

// ---------------- zero h[0] ----------------
__global__ void zero_state_kernel() {
    int i = blockIdx.x * blockDim.x + threadIdx.x;
    if (i < H * B) g_h[0][i] = 0.0f;
}

// ---------------- big GEMM: C[m][n] = A[m][:] . W[n][:] + b1[n] + b2[n] ----------------
#define BM 128
#define BN 128
#define BKT 16
#define LDT 132

__global__ __launch_bounds__(256) void gemm_bias_kernel(
    const float* __restrict__ x_in, const float* __restrict__ W,
    const float* __restrict__ b1, const float* __restrict__ b2,
    int K, int layer)
{
    const float* A = (layer == 0) ? x_in : g_hseq;
    __shared__ __align__(16) float As[BKT][LDT];
    __shared__ __align__(16) float Bs[BKT][LDT];
    int tid = threadIdx.x;
    int m0 = blockIdx.y * BM, n0 = blockIdx.x * BN;
    int tx = tid & 15, ty = tid >> 4;

    ull acc[8][4];
    #pragma unroll
    for (int i = 0; i < 8; i++)
        #pragma unroll
        for (int j = 0; j < 4; j++) acc[i][j] = 0ull;

    for (int k0 = 0; k0 < K; k0 += BKT) {
        #pragma unroll
        for (int r = 0; r < 2; r++) {
            int f = tid + r * 256;
            int m = f >> 2, kq = (f & 3) * 4;
            float4 va = __ldg((const float4*)&A[(size_t)(m0 + m) * K + k0 + kq]);
            As[kq + 0][m] = va.x; As[kq + 1][m] = va.y;
            As[kq + 2][m] = va.z; As[kq + 3][m] = va.w;
            float4 vb = __ldg((const float4*)&W[(size_t)(n0 + m) * K + k0 + kq]);
            Bs[kq + 0][m] = vb.x; Bs[kq + 1][m] = vb.y;
            Bs[kq + 2][m] = vb.z; Bs[kq + 3][m] = vb.w;
        }
        __syncthreads();
        #pragma unroll
        for (int k = 0; k < BKT; k++) {
            float4 a0 = *(const float4*)&As[k][ty * 8];
            float4 a1 = *(const float4*)&As[k][ty * 8 + 4];
            ulonglong2 bb0 = *(const ulonglong2*)&Bs[k][tx * 8];
            ulonglong2 bb1 = *(const ulonglong2*)&Bs[k][tx * 8 + 4];
            ull bb[4] = {bb0.x, bb0.y, bb1.x, bb1.y};
            float av[8] = {a0.x, a0.y, a0.z, a0.w, a1.x, a1.y, a1.z, a1.w};
            #pragma unroll
            for (int i = 0; i < 8; i++) {
                ull ad = pack2(av[i], av[i]);
                #pragma unroll
                for (int j = 0; j < 4; j++) fma2(acc[i][j], ad, bb[j]);
            }
        }
        __syncthreads();
    }

    float bs[8];
    #pragma unroll
    for (int j = 0; j < 8; j++) {
        int n = n0 + tx * 8 + j;
        bs[j] = __ldg(&b1[n]) + __ldg(&b2[n]);
    }
    #pragma unroll
    for (int i = 0; i < 8; i++) {
        int m = m0 + ty * 8 + i;
        float o[8];
        #pragma unroll
        for (int j = 0; j < 4; j++) {
            float lo, hi; unpack2(acc[i][j], lo, hi);
            o[j * 2] = lo + bs[j * 2]; o[j * 2 + 1] = hi + bs[j * 2 + 1];
        }
        float4* dst = (float4*)&g_xg[(size_t)m * G4 + n0 + tx * 8];
        dst[0] = make_float4(o[0], o[1], o[2], o[3]);
        dst[1] = make_float4(o[4], o[5], o[6], o[7]);
    }
}

// ---------------- persistent LSTM recurrence (all 256 steps in one launch) ----------------
// 128 CTAs x 512 threads. CTA owns 4 hidden units (64KB W slice in SMEM, loaded once).
// warp w: u = w&3 (unit), kq = w>>2 (k-quarter of 128). Thread: batch pair b0 = 2*lane.
// h is read through L1 (default cached loads): coherence is guaranteed because every
// CTA executes __threadfence() (gpu scope -> CCTL.IVALL, invalidates L1D) inside the
// grid barrier between producing h(t+1) and consuming it.
__global__ __launch_bounds__(512) void lstm_persist_kernel(int layer)
{
    extern __shared__ __align__(16) float Wd[];     // 64KB: [u][g][k][2]
    __shared__ __align__(16) ull red[3][4][32][4];  // 12KB: k-quarter partial sums

    int tid = threadIdx.x;
    int lane = tid & 31;
    int w = tid >> 5;
    int u = w & 3;
    int kq = w >> 2;           // 0..3
    int b0 = lane * 2;
    int j = blockIdx.x * 4 + u;

    // stage W slice once
    {
        const float4* src = (const float4*)&g_wdup[layer][(size_t)blockIdx.x * 16384];
        float4* dst = (float4*)Wd;
        #pragma unroll
        for (int i = 0; i < 8; i++) dst[tid + i * 512] = __ldg(&src[tid + i * 512]);
    }
    __syncthreads();

    // W addr for (g, kq*128 + kk): (g*512 + kq*128 + kk)*2 = g*1024 + kq*256 + kk*2
    const float* Wuk = Wd + u * 4096 + kq * 256;
    float c0 = 0.0f, c1 = 0.0f;

    for (int t = 0; t < S; t++) {
        // prefetch x gates early (DRAM latency hides under the k-loop)
        float xg0[4], xg1[4];
        if (kq == 0) {
            size_t base0, base1;
            if (layer == 0) {
                base0 = ((size_t)(b0 * S + t)) * G4 + j;
                base1 = ((size_t)((b0 + 1) * S + t)) * G4 + j;
            } else {
                base0 = ((size_t)(t * B + b0)) * G4 + j;
                base1 = base0 + G4;
            }
            #pragma unroll
            for (int g = 0; g < 4; g++) {
                xg0[g] = ldcs32(&g_xg[base0 + g * 512]);
                xg1[g] = ldcs32(&g_xg[base1 + g * 512]);
            }
        }

        ull acc[4] = {0ull, 0ull, 0ull, 0ull};
        if (t > 0) {
            // L1-cached h reads (deduped across the 4 unit-warps sharing this kq)
            const ull* hp = (const ull*)(g_h[t & 1] + (size_t)kq * 128 * 64 + b0);
            #pragma unroll 4
            for (int kk = 0; kk < 128; kk += 2) {
                ull h0 = hp[kk * 32];          // {h[k][b0], h[k][b0+1]}
                ull h1 = hp[(kk + 1) * 32];
                #pragma unroll
                for (int g = 0; g < 4; g++) {
                    ulonglong2 wv = *(const ulonglong2*)&Wuk[g * 1024 + kk * 2];
                    fma2(acc[g], h0, wv.x);
                    fma2(acc[g], h1, wv.y);
                }
            }
        }

        if (kq != 0) {
            #pragma unroll
            for (int g = 0; g < 4; g++) red[kq - 1][u][lane][g] = acc[g];
        }
        __syncthreads();

        if (kq == 0) {
            float ga[4][2];
            #pragma unroll
            for (int g = 0; g < 4; g++) {
                ull s = acc[g];
                #pragma unroll
                for (int q = 0; q < 3; q++) s = add2(s, red[q][u][lane][g]);
                unpack2(s, ga[g][0], ga[g][1]);
            }
            // batch b0
            float i0 = sigm(ga[0][0] + xg0[0]);
            float f0 = sigm(ga[1][0] + xg0[1]);
            float g0 = tanhf(ga[2][0] + xg0[2]);
            float o0 = sigm(ga[3][0] + xg0[3]);
            c0 = f0 * c0 + i0 * g0;
            float hh0 = o0 * tanhf(c0);
            // batch b0+1
            float i1 = sigm(ga[0][1] + xg1[0]);
            float f1 = sigm(ga[1][1] + xg1[1]);
            float g1 = tanhf(ga[2][1] + xg1[2]);
            float o1 = sigm(ga[3][1] + xg1[3]);
            c1 = f1 * c1 + i1 * g1;
            float hh1 = o1 * tanhf(c1);

            *(float2*)&g_h[(t + 1) & 1][j * 64 + b0] = make_float2(hh0, hh1);
            if (layer == 0) {
                g_hseq[((size_t)t * 64 + b0) * 512 + j] = hh0;
                g_hseq[((size_t)t * 64 + b0 + 1) * 512 + j] = hh1;
            }
        }

        // grid barrier (skip after last step; kernel boundary handles final visibility)
        if (t != S - 1) {
            __syncthreads();
            if (tid == 0) {
                unsigned gen = g_bar_gen;
                __threadfence();   // drain h stores to L2
                if (atomicAdd(&g_bar_cnt, 1u) == NCTA - 1) {
                    g_bar_cnt = 0;
                    __threadfence();
                    g_bar_gen = gen + 1;
                } else {
                    while (g_bar_gen == gen) { }
                }
                __threadfence();   // gpu-scope fence -> CCTL.IVALL: invalidate L1D so
                                   // next step's L1-cached h reads are coherent
            }
            __syncthreads();
        }
    }
}

// ---------------- final FC: out[b][o] = h_last[:,b] . W_fc[o][:] + b_fc[o] ----------------
__global__ void fc_kernel(const float* __restrict__ Wfc, const float* __restrict__ bfc,
                          float* __restrict__ out)
{
    __shared__ float hcol[H];
    int b = blockIdx.x;
    int o = threadIdx.x;   // 64 threads
    for (int k = o; k < H; k += 64) hcol[k] = g_h[0][k * 64 + b];
    __syncthreads();
    float acc = __ldg(&bfc[o]);
    #pragma unroll 8
    for (int k = 0; k < H; k++) acc += hcol[k] * __ldg(&Wfc[o * 512 + k]);
    out[b * 64 + o] = acc;
}

// ---------------- launch ----------------
extern "C" void kernel_launch(void* const* d_in, const int* in_sizes, int n_in,
                              void* d_out, int out_size)
{
    const float* x      = (const float*)d_in[0];
    const float* W_ih_0 = (const float*)d_in[1];
    const float* W_hh_0 = (const float*)d_in[2];
    const float* b_ih_0 = (const float*)d_in[3];
    const float* b_hh_0 = (const float*)d_in[4];
    const float* W_ih_1 = (const float*)d_in[5];
    const float* W_hh_1 = (const float*)d_in[6];
    const float* b_ih_1 = (const float*)d_in[7];
    const float* b_hh_1 = (const float*)d_in[8];
    const float* W_fc   = (const float*)d_in[9];
    const float* b_fc   = (const float*)d_in[10];
    float* out = (float*)d_out;

    cudaFuncSetAttribute(lstm_persist_kernel, cudaFuncAttributeMaxDynamicSharedMemorySize, 65536);

    prep_wdup_kernel<<<8192, 256>>>(W_hh_0, W_hh_1);

    // ---- layer 0 ----
    zero_state_kernel<<<128, 256>>>();
    gemm_bias_kernel<<<dim3(16, 128), 256>>>(x, W_ih_0, b_ih_0, b_hh_0, INSZ, 0);
    lstm_persist_kernel<<<NCTA, 512, 65536>>>(0);

    // ---- layer 1 ----
    zero_state_kernel<<<128, 256>>>();
    gemm_bias_kernel<<<dim3(16, 128), 256>>>(x, W_ih_1, b_ih_1, b_hh_1, H, 1);
    lstm_persist_kernel<<<NCTA, 512, 65536>>>(1);

    // ---- head ----
    fc_kernel<<<64, 64>>>(W_fc, b_fc, out);
}

// round 5
// speedup vs baseline: 3.4196x; 1.0013x over previous
#include <cuda_runtime.h>
#include <math.h>

#define B 64
#define S 256
#define INSZ 128
#define H 512
#define G4 2048          // 4*H
#define NTOK (B*S)       // 16384
#define NCTA 128

// ---------------- scratch (device globals; no allocation allowed) ----------------
__device__ float g_xg[(size_t)NTOK * G4];        // 128 MB: gate pre-activations per layer
__device__ float g_hseq[(size_t)NTOK * H];       // 32 MB: layer-0 hidden sequence (rows n = t*64+b)
__device__ float g_h[2][H * B];                  // double-buffered hidden state, layout [k][b]
__device__ float g_wdup[2][(size_t)G4 * H * 2];  // 16 MB: W_hh duplicated {w,w}, blocked per CTA

// grid barrier state (persists across replays; relative-gen logic is replay-safe)
__device__ unsigned g_bar_cnt = 0;
__device__ volatile unsigned g_bar_gen = 0;

typedef unsigned long long ull;

__device__ __forceinline__ ull pack2(float lo, float hi) {
    ull r; asm("mov.b64 %0, {%1, %2};" : "=l"(r) : "f"(lo), "f"(hi)); return r;
}
__device__ __forceinline__ void unpack2(ull v, float& lo, float& hi) {
    asm("mov.b64 {%0, %1}, %2;" : "=f"(lo), "=f"(hi) : "l"(v));
}
__device__ __forceinline__ void fma2(ull& d, ull a, ull b) {
    asm("fma.rn.f32x2 %0, %1, %2, %0;" : "+l"(d) : "l"(a), "l"(b));
}
__device__ __forceinline__ ull add2(ull a, ull b) {
    ull r; asm("add.rn.f32x2 %0, %1, %2;" : "=l"(r) : "l"(a), "l"(b)); return r;
}
__device__ __forceinline__ float ldcs32(const float* p) {
    float v; asm volatile("ld.global.cs.b32 %0, [%1];" : "=f"(v) : "l"(p)); return v;
}
__device__ __forceinline__ float sigm(float x) { return 1.0f / (1.0f + __expf(-x)); }

// ---------------- prep: duplicate W_hh into CTA-blocked {w,w} layout ----------------
__global__ void prep_wdup_kernel(const float* __restrict__ W0, const float* __restrict__ W1) {
    int idx = blockIdx.x * blockDim.x + threadIdx.x;   // 2 * 2^20 total
    int l = idx >> 20;
    int r = idx & ((1 << 20) - 1);
    int j = r >> 11;
    int g = (r >> 9) & 3;
    int k = r & 511;
    const float* W = l ? W1 : W0;
    float v = W[(g * 512 + j) * 512 + k];
    float* dst = &g_wdup[l][(((size_t)(j * 4 + g)) * 512 + k) * 2];
    dst[0] = v; dst[1] = v;
}

// ---------------- zero h[0] ----------------
__global__ void zero_state_kernel() {
    int i = blockIdx.x * blockDim.x + threadIdx.x;
    if (i < H * B) g_h[0][i] = 0.0f;
}

// ---------------- big GEMM: C[m][n] = A[m][:] . W[n][:] + b1[n] + b2[n] ----------------
#define BM 128
#define BN 128
#define BKT 16
#define LDT 132

__global__ __launch_bounds__(256) void gemm_bias_kernel(
    const float* __restrict__ x_in, const float* __restrict__ W,
    const float* __restrict__ b1, const float* __restrict__ b2,
    int K, int layer)
{
    const float* A = (layer == 0) ? x_in : g_hseq;
    __shared__ __align__(16) float As[BKT][LDT];
    __shared__ __align__(16) float Bs[BKT][LDT];
    int tid = threadIdx.x;
    int m0 = blockIdx.y * BM, n0 = blockIdx.x * BN;
    int tx = tid & 15, ty = tid >> 4;

    ull acc[8][4];
    #pragma unroll
    for (int i = 0; i < 8; i++)
        #pragma unroll
        for (int j = 0; j < 4; j++) acc[i][j] = 0ull;

    for (int k0 = 0; k0 < K; k0 += BKT) {
        #pragma unroll
        for (int r = 0; r < 2; r++) {
            int f = tid + r * 256;
            int m = f >> 2, kq = (f & 3) * 4;
            float4 va = __ldg((const float4*)&A[(size_t)(m0 + m) * K + k0 + kq]);
            As[kq + 0][m] = va.x; As[kq + 1][m] = va.y;
            As[kq + 2][m] = va.z; As[kq + 3][m] = va.w;
            float4 vb = __ldg((const float4*)&W[(size_t)(n0 + m) * K + k0 + kq]);
            Bs[kq + 0][m] = vb.x; Bs[kq + 1][m] = vb.y;
            Bs[kq + 2][m] = vb.z; Bs[kq + 3][m] = vb.w;
        }
        __syncthreads();
        #pragma unroll
        for (int k = 0; k < BKT; k++) {
            float4 a0 = *(const float4*)&As[k][ty * 8];
            float4 a1 = *(const float4*)&As[k][ty * 8 + 4];
            ulonglong2 bb0 = *(const ulonglong2*)&Bs[k][tx * 8];
            ulonglong2 bb1 = *(const ulonglong2*)&Bs[k][tx * 8 + 4];
            ull bb[4] = {bb0.x, bb0.y, bb1.x, bb1.y};
            float av[8] = {a0.x, a0.y, a0.z, a0.w, a1.x, a1.y, a1.z, a1.w};
            #pragma unroll
            for (int i = 0; i < 8; i++) {
                ull ad = pack2(av[i], av[i]);
                #pragma unroll
                for (int j = 0; j < 4; j++) fma2(acc[i][j], ad, bb[j]);
            }
        }
        __syncthreads();
    }

    float bs[8];
    #pragma unroll
    for (int j = 0; j < 8; j++) {
        int n = n0 + tx * 8 + j;
        bs[j] = __ldg(&b1[n]) + __ldg(&b2[n]);
    }
    #pragma unroll
    for (int i = 0; i < 8; i++) {
        int m = m0 + ty * 8 + i;
        float o[8];
        #pragma unroll
        for (int j = 0; j < 4; j++) {
            float lo, hi; unpack2(acc[i][j], lo, hi);
            o[j * 2] = lo + bs[j * 2]; o[j * 2 + 1] = hi + bs[j * 2 + 1];
        }
        float4* dst = (float4*)&g_xg[(size_t)m * G4 + n0 + tx * 8];
        dst[0] = make_float4(o[0], o[1], o[2], o[3]);
        dst[1] = make_float4(o[4], o[5], o[6], o[7]);
    }
}

// ---------------- persistent LSTM recurrence (all 256 steps in one launch) ----------------
// 128 CTAs x 512 threads. CTA owns 4 hidden units (64KB W slice in SMEM, loaded once).
// warp w: u = w&3 (unit), kq = w>>2 (k-quarter of 128). Thread: batch pair b0 = 2*lane.
// h is read through L1 (default cached loads): coherence is guaranteed because every
// CTA executes __threadfence() (gpu scope -> CCTL.IVALL, invalidates L1D) inside the
// grid barrier between producing h(t+1) and consuming it.
__global__ __launch_bounds__(512) void lstm_persist_kernel(int layer)
{
    extern __shared__ __align__(16) float Wd[];     // 64KB: [u][g][k][2]
    __shared__ __align__(16) ull red[3][4][32][4];  // 12KB: k-quarter partial sums

    int tid = threadIdx.x;
    int lane = tid & 31;
    int w = tid >> 5;
    int u = w & 3;
    int kq = w >> 2;           // 0..3
    int b0 = lane * 2;
    int j = blockIdx.x * 4 + u;

    // stage W slice once
    {
        const float4* src = (const float4*)&g_wdup[layer][(size_t)blockIdx.x * 16384];
        float4* dst = (float4*)Wd;
        #pragma unroll
        for (int i = 0; i < 8; i++) dst[tid + i * 512] = __ldg(&src[tid + i * 512]);
    }
    __syncthreads();

    // W addr for (g, kq*128 + kk): (g*512 + kq*128 + kk)*2 = g*1024 + kq*256 + kk*2
    const float* Wuk = Wd + u * 4096 + kq * 256;
    float c0 = 0.0f, c1 = 0.0f;

    for (int t = 0; t < S; t++) {
        // prefetch x gates early (DRAM latency hides under the k-loop)
        float xg0[4], xg1[4];
        if (kq == 0) {
            size_t base0, base1;
            if (layer == 0) {
                base0 = ((size_t)(b0 * S + t)) * G4 + j;
                base1 = ((size_t)((b0 + 1) * S + t)) * G4 + j;
            } else {
                base0 = ((size_t)(t * B + b0)) * G4 + j;
                base1 = base0 + G4;
            }
            #pragma unroll
            for (int g = 0; g < 4; g++) {
                xg0[g] = ldcs32(&g_xg[base0 + g * 512]);
                xg1[g] = ldcs32(&g_xg[base1 + g * 512]);
            }
        }

        ull acc[4] = {0ull, 0ull, 0ull, 0ull};
        if (t > 0) {
            // L1-cached h reads (deduped across the 4 unit-warps sharing this kq)
            const ull* hp = (const ull*)(g_h[t & 1] + (size_t)kq * 128 * 64 + b0);
            #pragma unroll 4
            for (int kk = 0; kk < 128; kk += 2) {
                ull h0 = hp[kk * 32];          // {h[k][b0], h[k][b0+1]}
                ull h1 = hp[(kk + 1) * 32];
                #pragma unroll
                for (int g = 0; g < 4; g++) {
                    ulonglong2 wv = *(const ulonglong2*)&Wuk[g * 1024 + kk * 2];
                    fma2(acc[g], h0, wv.x);
                    fma2(acc[g], h1, wv.y);
                }
            }
        }

        if (kq != 0) {
            #pragma unroll
            for (int g = 0; g < 4; g++) red[kq - 1][u][lane][g] = acc[g];
        }
        __syncthreads();

        if (kq == 0) {
            float ga[4][2];
            #pragma unroll
            for (int g = 0; g < 4; g++) {
                ull s = acc[g];
                #pragma unroll
                for (int q = 0; q < 3; q++) s = add2(s, red[q][u][lane][g]);
                unpack2(s, ga[g][0], ga[g][1]);
            }
            // batch b0
            float i0 = sigm(ga[0][0] + xg0[0]);
            float f0 = sigm(ga[1][0] + xg0[1]);
            float g0 = tanhf(ga[2][0] + xg0[2]);
            float o0 = sigm(ga[3][0] + xg0[3]);
            c0 = f0 * c0 + i0 * g0;
            float hh0 = o0 * tanhf(c0);
            // batch b0+1
            float i1 = sigm(ga[0][1] + xg1[0]);
            float f1 = sigm(ga[1][1] + xg1[1]);
            float g1 = tanhf(ga[2][1] + xg1[2]);
            float o1 = sigm(ga[3][1] + xg1[3]);
            c1 = f1 * c1 + i1 * g1;
            float hh1 = o1 * tanhf(c1);

            *(float2*)&g_h[(t + 1) & 1][j * 64 + b0] = make_float2(hh0, hh1);
            if (layer == 0) {
                g_hseq[((size_t)t * 64 + b0) * 512 + j] = hh0;
                g_hseq[((size_t)t * 64 + b0 + 1) * 512 + j] = hh1;
            }
        }

        // grid barrier (skip after last step; kernel boundary handles final visibility)
        if (t != S - 1) {
            __syncthreads();
            if (tid == 0) {
                unsigned gen = g_bar_gen;
                __threadfence();   // drain h stores to L2
                if (atomicAdd(&g_bar_cnt, 1u) == NCTA - 1) {
                    g_bar_cnt = 0;
                    __threadfence();
                    g_bar_gen = gen + 1;
                } else {
                    while (g_bar_gen == gen) { }
                }
                __threadfence();   // gpu-scope fence -> CCTL.IVALL: invalidate L1D so
                                   // next step's L1-cached h reads are coherent
            }
            __syncthreads();
        }
    }
}

// ---------------- final FC: out[b][o] = h_last[:,b] . W_fc[o][:] + b_fc[o] ----------------
__global__ void fc_kernel(const float* __restrict__ Wfc, const float* __restrict__ bfc,
                          float* __restrict__ out)
{
    __shared__ float hcol[H];
    int b = blockIdx.x;
    int o = threadIdx.x;   // 64 threads
    for (int k = o; k < H; k += 64) hcol[k] = g_h[0][k * 64 + b];
    __syncthreads();
    float acc = __ldg(&bfc[o]);
    #pragma unroll 8
    for (int k = 0; k < H; k++) acc += hcol[k] * __ldg(&Wfc[o * 512 + k]);
    out[b * 64 + o] = acc;
}

// ---------------- launch ----------------
extern "C" void kernel_launch(void* const* d_in, const int* in_sizes, int n_in,
                              void* d_out, int out_size)
{
    const float* x      = (const float*)d_in[0];
    const float* W_ih_0 = (const float*)d_in[1];
    const float* W_hh_0 = (const float*)d_in[2];
    const float* b_ih_0 = (const float*)d_in[3];
    const float* b_hh_0 = (const float*)d_in[4];
    const float* W_ih_1 = (const float*)d_in[5];
    const float* W_hh_1 = (const float*)d_in[6];
    const float* b_ih_1 = (const float*)d_in[7];
    const float* b_hh_1 = (const float*)d_in[8];
    const float* W_fc   = (const float*)d_in[9];
    const float* b_fc   = (const float*)d_in[10];
    float* out = (float*)d_out;

    cudaFuncSetAttribute(lstm_persist_kernel, cudaFuncAttributeMaxDynamicSharedMemorySize, 65536);

    prep_wdup_kernel<<<8192, 256>>>(W_hh_0, W_hh_1);

    // ---- layer 0 ----
    zero_state_kernel<<<128, 256>>>();
    gemm_bias_kernel<<<dim3(16, 128), 256>>>(x, W_ih_0, b_ih_0, b_hh_0, INSZ, 0);
    lstm_persist_kernel<<<NCTA, 512, 65536>>>(0);

    // ---- layer 1 ----
    zero_state_kernel<<<128, 256>>>();
    gemm_bias_kernel<<<dim3(16, 128), 256>>>(x, W_ih_1, b_ih_1, b_hh_1, H, 1);
    lstm_persist_kernel<<<NCTA, 512, 65536>>>(1);

    // ---- head ----
    fc_kernel<<<64, 64>>>(W_fc, b_fc, out);
}